// round 14
// baseline (speedup 1.0000x reference)
#include <cuda_runtime.h>
#include <cuda_fp16.h>
#include <cstdint>

// CharBiLSTMEmbedder: N=32768, T=20, E=H=50, V=200, out [N,2H] fp32.
//
// Round-14: M=32 rows per warp — both m16 A-tiles share every B fragment, so
// the dominant crossbar traffic (static W reloads) halves per word.
// 384 threads / 12 warps / 384 words per CTA (reg cap 170 fits creg[52]).
// Everything else per R13: fp16 mma.sync single-term GEMM, gate-pair B layout
// (shuffle-free epilogue), f16x2 h-channel, fp32 c-channel, zero-barrier
// warp-private A, global counting sort by length desc, fused aux kernel.

#define TT 20
#define HH 50
#define EE 50
#define VV 200
#define G4 200
#define NB 208           // padded B rows (26 tiles x 8)
#define KP 64            // padded K
#define NWB 384          // words per CTA
#define NTH 384
#define NMAX 65536
#define AUXTH 512

// smem offsets (A/B rows padded to 144B)
#define OFF_A    0        // 384*144 = 55296
#define OFF_B    55296    // 208*144 = 29952 -> 85248
#define OFF_XW   85248    // 200*200*2 = 80000 -> 165248
#define OFF_CH   165248   // 20*384 = 7680 -> 172928
#define OFF_LEN  172928   // 384*4 = 1536
#define OFF_PERM 174464   // 384*4 = 1536
#define SMEM_BYTES 176000

#define H2_HALF 0x38003800u   // (0.5, 0.5) fp16x2

__device__ __half g_xwh[2 * VV * G4];       // [dir][v][cell*4+gate]
__device__ __half g_wf[2 * NB * KP];        // [dir][n(gate-pair layout)][k]
__device__ int g_perm[NMAX];

// ---------- helpers ----------
__device__ __forceinline__ uint32_t s2u(const void* p) {
    uint32_t a;
    asm("{ .reg .u64 t; cvta.to.shared.u64 t, %1; cvt.u32.u64 %0, t; }"
        : "=r"(a) : "l"(p));
    return a;
}
__device__ __forceinline__ float tanha(float x) {
    float y; asm("tanh.approx.f32 %0, %1;" : "=f"(y) : "f"(x)); return y;
}
__device__ __forceinline__ float sigt(float x) {
    return fmaf(tanha(0.5f * x), 0.5f, 0.5f);
}
__device__ __forceinline__ uint32_t pack_h2(float hi, float lo) {
    uint32_t d;
    asm("cvt.rn.f16x2.f32 %0, %1, %2;" : "=r"(d) : "f"(hi), "f"(lo));
    return d;
}
__device__ __forceinline__ uint32_t h2tanh(uint32_t x) {
    uint32_t y; asm("tanh.approx.f16x2 %0, %1;" : "=r"(y) : "r"(x)); return y;
}
__device__ __forceinline__ uint32_t h2fma(uint32_t a, uint32_t b, uint32_t c) {
    uint32_t d;
    asm("fma.rn.f16x2 %0, %1, %2, %3;" : "=r"(d) : "r"(a), "r"(b), "r"(c));
    return d;
}
__device__ __forceinline__ uint32_t h2mul(uint32_t a, uint32_t b) {
    uint32_t d;
    asm("mul.rn.f16x2 %0, %1, %2;" : "=r"(d) : "r"(a), "r"(b));
    return d;
}
__device__ __forceinline__ void ldsm4(uint32_t& r0, uint32_t& r1, uint32_t& r2,
                                      uint32_t& r3, uint32_t addr) {
    asm volatile("ldmatrix.sync.aligned.m8n8.x4.shared.b16 {%0,%1,%2,%3}, [%4];"
                 : "=r"(r0), "=r"(r1), "=r"(r2), "=r"(r3) : "r"(addr));
}
__device__ __forceinline__ void mma_f16(float& d0, float& d1, float& d2, float& d3,
                                        uint32_t a0, uint32_t a1, uint32_t a2, uint32_t a3,
                                        uint32_t b0, uint32_t b1) {
    asm volatile("mma.sync.aligned.m16n8k16.row.col.f32.f16.f16.f32 "
                 "{%0,%1,%2,%3}, {%4,%5,%6,%7}, {%8,%9}, {%0,%1,%2,%3};"
                 : "+f"(d0), "+f"(d1), "+f"(d2), "+f"(d3)
                 : "r"(a0), "r"(a1), "r"(a2), "r"(a3), "r"(b0), "r"(b1));
}

// ---------- fused aux: block 0 = counting sort; blocks 1.. = tables ----------
__global__ void __launch_bounds__(AUXTH)
aux_all(const int* __restrict__ lens, int N,
        const float* __restrict__ emb,
        const float* __restrict__ Wih_f, const float* __restrict__ bih_f,
        const float* __restrict__ bhh_f,
        const float* __restrict__ Wih_b, const float* __restrict__ bih_b,
        const float* __restrict__ bhh_b,
        const float* __restrict__ Whh_f, const float* __restrict__ Whh_b) {
    const int tid = threadIdx.x;
    if (blockIdx.x == 0) {
        __shared__ int hist[TT + 1];
        __shared__ int base[TT + 1];
        if (tid <= TT) hist[tid] = 0;
        __syncthreads();
        for (int i = tid; i < N; i += AUXTH) {
            int L = lens[i]; if (L < 0) L = 0; if (L > TT) L = TT;
            atomicAdd(&hist[L], 1);
        }
        __syncthreads();
        if (tid == 0) {
            int off = 0;
            for (int q = TT; q >= 0; --q) { base[q] = off; off += hist[q]; }
        }
        __syncthreads();
        for (int i = tid; i < N; i += AUXTH) {
            int L = lens[i]; if (L < 0) L = 0; if (L > TT) L = TT;
            int p = atomicAdd(&base[L], 1);
            g_perm[p] = i;        // bin order = atomic order; outputs perm-invariant
        }
        return;
    }

    int idx = (blockIdx.x - 1) * AUXTH + tid;
    if (idx < 2 * VV * HH) {              // xw: all 4 gates of (dir, v, j)
        int dir = idx / (VV * HH);
        int r   = idx % (VV * HH);
        int v   = r / HH, j = r % HH;
        const float* Wih = dir ? Wih_b : Wih_f;
        const float* bih = dir ? bih_b : bih_f;
        const float* bhh = dir ? bhh_b : bhh_f;
        float a0 = 0.f, a1 = 0.f, a2 = 0.f, a3 = 0.f;
        if (v != 0) {                     // padding_idx 0 -> zero embedding row
            const float2* er = (const float2*)(emb + v * EE);
            const float2* w0 = (const float2*)(Wih + (0 * HH + j) * EE);
            const float2* w1 = (const float2*)(Wih + (1 * HH + j) * EE);
            const float2* w2 = (const float2*)(Wih + (2 * HH + j) * EE);
            const float2* w3 = (const float2*)(Wih + (3 * HH + j) * EE);
#pragma unroll
            for (int e = 0; e < EE / 2; ++e) {
                float2 ev = er[e];
                float2 x0 = w0[e], x1 = w1[e], x2 = w2[e], x3 = w3[e];
                a0 += ev.x * x0.x + ev.y * x0.y;
                a1 += ev.x * x1.x + ev.y * x1.y;
                a2 += ev.x * x2.x + ev.y * x2.y;
                a3 += ev.x * x3.x + ev.y * x3.y;
            }
        }
        __half* dst = g_xwh + (size_t)dir * VV * G4 + v * G4 + j * 4;
        dst[0] = __float2half(a0 + bih[0 * HH + j] + bhh[0 * HH + j]);
        dst[1] = __float2half(a1 + bih[1 * HH + j] + bhh[1 * HH + j]);
        dst[2] = __float2half(a2 + bih[2 * HH + j] + bhh[2 * HH + j]);
        dst[3] = __float2half(a3 + bih[3 * HH + j] + bhh[3 * HH + j]);
        return;
    }
    int i2 = idx - 2 * VV * HH;
    if (i2 >= 2 * NB * KP) return;        // W fp16: gate-pair layout
    int dir = i2 / (NB * KP);
    int r   = i2 % (NB * KP);
    int n   = r / KP;
    int k   = r % KP;
    int gate, cell;
    if (n < 104) {                        // (i,f) tiles
        int m = n >> 3, j = n & 7;
        gate = (j & 1) ? 1 : 0;
        cell = 4 * m + (j >> 1);
    } else {                              // (g,o) tiles
        int n2 = n - 104;
        int m = n2 >> 3, j = n2 & 7;
        gate = (j & 1) ? 3 : 2;
        cell = 4 * m + (j >> 1);
    }
    const float* Whh = dir ? Whh_b : Whh_f;
    float w = (cell < HH && k < HH) ? Whh[(gate * HH + cell) * HH + k] : 0.0f;
    g_wf[i2] = __float2half(w);
}

// ---------- main kernel ----------
__global__ void __launch_bounds__(NTH, 1)
lstm_mma_kernel(const int* __restrict__ chars, const int* __restrict__ lens,
                float* __restrict__ out, int N) {
    extern __shared__ __align__(16) unsigned char smraw[];
    const uint32_t su = s2u(smraw);
    __half* sXWH = (__half*)(smraw + OFF_XW);
    unsigned char* sCh = smraw + OFF_CH;
    int* sLen  = (int*)(smraw + OFF_LEN);
    int* sPerm = (int*)(smraw + OFF_PERM);

    const int tid   = threadIdx.x;
    const int dir   = blockIdx.y;
    const int wbase = blockIdx.x * NWB;

    if (tid < NWB) {
        int gi = wbase + tid;
        int p = (gi < N) ? g_perm[gi] : -1;
        sPerm[tid] = p;
        int L = (p >= 0) ? lens[p] : 0;
        if (L < 0) L = 0; if (L > TT) L = TT;
        sLen[tid] = L;
    }
    // zero A (h starts 0; k-pad stays 0)
    {
        uint4* a4 = (uint4*)(smraw + OFF_A);
        uint4 z = make_uint4(0, 0, 0, 0);
        for (int i = tid; i < (NWB * 144) / 16; i += NTH) a4[i] = z;
    }
    // stage B (rows of 64 fp16 = 8 uint4, stride 144B)
    {
        const uint4* src = (const uint4*)(g_wf + (size_t)dir * NB * KP);
        for (int i = tid; i < NB * 8; i += NTH) {
            int n = i >> 3, j = i & 7;
            *(uint4*)(smraw + OFF_B + n * 144 + j * 16) = src[i];
        }
    }
    // stage xw fp16 (5000 uint4)
    {
        const uint4* src = (const uint4*)(g_xwh + (size_t)dir * VV * G4);
        uint4* dst = (uint4*)sXWH;
        for (int i = tid; i < (VV * G4 * 2) / 16; i += NTH) dst[i] = src[i];
    }
    __syncthreads();
    for (int i = tid; i < NWB * TT; i += NTH) {
        int w = i / TT, t = i % TT;
        int p = sPerm[w];
        sCh[t * NWB + w] = (unsigned char)((p >= 0) ? chars[p * TT + t] : 0);
    }
    __syncthreads();

    const int warp = tid >> 5, lane = tid & 31;
    const int R0 = warp * 32;                   // 32-row m-tile per warp
    const int tig = lane & 3;
    const int g0 = R0 + (lane >> 2);            // 4 words per lane
    const int g1 = g0 + 8;
    const int g2 = g0 + 16;
    const int g3 = g0 + 24;
    const int len0 = sLen[g0], len1 = sLen[g1];
    const int len2 = sLen[g2], len3 = sLen[g3];
    const int warpmax = sLen[R0];               // sorted desc

    const uint32_t aBase0 = su + OFF_A + (uint32_t)(R0 + (lane & 15)) * 144
                          + (uint32_t)((lane >> 4) & 1) * 16;
    const uint32_t aBase1 = aBase0 + 16u * 144u;
    const uint32_t bAddr = su + OFF_B + (uint32_t)(lane & 7) * 144
                         + (uint32_t)(lane >> 3) * 16;

    float c0[13], c1[13], c2[13], c3[13];
#pragma unroll
    for (int i = 0; i < 13; ++i) { c0[i] = 0.f; c1[i] = 0.f; c2[i] = 0.f; c3[i] = 0.f; }

    for (int s = 0; s < warpmax; ++s) {
        uint32_t a0[4][4], a1[4][4];
#pragma unroll
        for (int kk = 0; kk < 4; ++kk)
            ldsm4(a0[kk][0], a0[kk][1], a0[kk][2], a0[kk][3], aBase0 + kk * 32);
#pragma unroll
        for (int kk = 0; kk < 4; ++kk)
            ldsm4(a1[kk][0], a1[kk][1], a1[kk][2], a1[kk][3], aBase1 + kk * 32);

        int t0 = dir ? (len0 - 1 - s) : s; if (t0 < 0) t0 = 0;
        int t1 = dir ? (len1 - 1 - s) : s; if (t1 < 0) t1 = 0;
        int t2 = dir ? (len2 - 1 - s) : s; if (t2 < 0) t2 = 0;
        int t3 = dir ? (len3 - 1 - s) : s; if (t3 < 0) t3 = 0;
        const int ch0 = sCh[t0 * NWB + g0];
        const int ch1 = sCh[t1 * NWB + g1];
        const int ch2 = sCh[t2 * NWB + g2];
        const int ch3 = sCh[t3 * NWB + g3];
        const bool u0 = (s < len0), u1 = (s < len1);
        const bool u2 = (s < len2), u3 = (s < len3);
        const __half* xr0 = sXWH + ch0 * G4;
        const __half* xr1 = sXWH + ch1 * G4;
        const __half* xr2 = sXWH + ch2 * G4;
        const __half* xr3 = sXWH + ch3 * G4;

#pragma unroll
        for (int m = 0; m < 13; ++m) {
            const int cell = 4 * m + tig;
            const uint32_t bIF = bAddr + (uint32_t)(m * 8) * 144;
            const uint32_t bGO = bIF + (uint32_t)(104) * 144;
            uint32_t p0, p1, p2, p3, q0, q1, q2, q3;
            uint32_t r0, r1, r2, r3, w0, w1, w2, w3;
            ldsm4(p0, p1, p2, p3, bIF);          // IF k 0..31
            ldsm4(q0, q1, q2, q3, bIF + 64);     // IF k 32..63
            ldsm4(r0, r1, r2, r3, bGO);          // GO k 0..31
            ldsm4(w0, w1, w2, w3, bGO + 64);     // GO k 32..63

            // m-tile 0 (rows R0..R0+15): words g0 (rows), g1 (+8)
            float eI0 = 0.f, eI1 = 0.f, eI2 = 0.f, eI3 = 0.f;   // IF
            float eG0 = 0.f, eG1 = 0.f, eG2 = 0.f, eG3 = 0.f;   // GO
            mma_f16(eI0, eI1, eI2, eI3, a0[0][0], a0[0][1], a0[0][2], a0[0][3], p0, p1);
            mma_f16(eG0, eG1, eG2, eG3, a0[0][0], a0[0][1], a0[0][2], a0[0][3], r0, r1);
            mma_f16(eI0, eI1, eI2, eI3, a0[1][0], a0[1][1], a0[1][2], a0[1][3], p2, p3);
            mma_f16(eG0, eG1, eG2, eG3, a0[1][0], a0[1][1], a0[1][2], a0[1][3], r2, r3);
            mma_f16(eI0, eI1, eI2, eI3, a0[2][0], a0[2][1], a0[2][2], a0[2][3], q0, q1);
            mma_f16(eG0, eG1, eG2, eG3, a0[2][0], a0[2][1], a0[2][2], a0[2][3], w0, w1);
            mma_f16(eI0, eI1, eI2, eI3, a0[3][0], a0[3][1], a0[3][2], a0[3][3], q2, q3);
            mma_f16(eG0, eG1, eG2, eG3, a0[3][0], a0[3][1], a0[3][2], a0[3][3], w2, w3);

            // m-tile 1 (rows R0+16..R0+31): words g2, g3 — SAME B fragments
            float vI0 = 0.f, vI1 = 0.f, vI2 = 0.f, vI3 = 0.f;
            float vG0 = 0.f, vG1 = 0.f, vG2 = 0.f, vG3 = 0.f;
            mma_f16(vI0, vI1, vI2, vI3, a1[0][0], a1[0][1], a1[0][2], a1[0][3], p0, p1);
            mma_f16(vG0, vG1, vG2, vG3, a1[0][0], a1[0][1], a1[0][2], a1[0][3], r0, r1);
            mma_f16(vI0, vI1, vI2, vI3, a1[1][0], a1[1][1], a1[1][2], a1[1][3], p2, p3);
            mma_f16(vG0, vG1, vG2, vG3, a1[1][0], a1[1][1], a1[1][2], a1[1][3], r2, r3);
            mma_f16(vI0, vI1, vI2, vI3, a1[2][0], a1[2][1], a1[2][2], a1[2][3], q0, q1);
            mma_f16(vG0, vG1, vG2, vG3, a1[2][0], a1[2][1], a1[2][2], a1[2][3], w0, w1);
            mma_f16(vI0, vI1, vI2, vI3, a1[3][0], a1[3][1], a1[3][2], a1[3][3], q2, q3);
            mma_f16(vG0, vG1, vG2, vG3, a1[3][0], a1[3][1], a1[3][2], a1[3][3], w2, w3);

            if (m < 12 || tig < 2) {             // cell < 50
                // c-channel fp32 for all 4 words
                uint2 xq0 = *(const uint2*)(xr0 + cell * 4);
                uint2 xq1 = *(const uint2*)(xr1 + cell * 4);
                uint2 xq2 = *(const uint2*)(xr2 + cell * 4);
                uint2 xq3 = *(const uint2*)(xr3 + cell * 4);
                float2 xifa = __half22float2(*(__half2*)&xq0.x);
                float2 xgoa = __half22float2(*(__half2*)&xq0.y);
                float2 xifb = __half22float2(*(__half2*)&xq1.x);
                float2 xgob = __half22float2(*(__half2*)&xq1.y);
                float2 xifc = __half22float2(*(__half2*)&xq2.x);
                float2 xgoc = __half22float2(*(__half2*)&xq2.y);
                float2 xifd = __half22float2(*(__half2*)&xq3.x);
                float2 xgod = __half22float2(*(__half2*)&xq3.y);

                float gi0 = eI0 + xifa.x, gf0 = eI1 + xifa.y;
                float gg0 = eG0 + xgoa.x, go0 = eG1 + xgoa.y;
                float gi1 = eI2 + xifb.x, gf1 = eI3 + xifb.y;
                float gg1 = eG2 + xgob.x, go1 = eG3 + xgob.y;
                float gi2 = vI0 + xifc.x, gf2 = vI1 + xifc.y;
                float gg2 = vG0 + xgoc.x, go2 = vG1 + xgoc.y;
                float gi3 = vI2 + xifd.x, gf3 = vI3 + xifd.y;
                float gg3 = vG2 + xgod.x, go3 = vG3 + xgod.y;

                float cn0 = sigt(gf0) * c0[m] + sigt(gi0) * tanha(gg0);
                float cn1 = sigt(gf1) * c1[m] + sigt(gi1) * tanha(gg1);
                float cn2 = sigt(gf2) * c2[m] + sigt(gi2) * tanha(gg2);
                float cn3 = sigt(gf3) * c3[m] + sigt(gi3) * tanha(gg3);

                // h-channel packed f16x2: h = sigma(o) * tanh(c)
                uint32_t cnA = pack_h2(cn1, cn0);
                uint32_t cnB = pack_h2(cn3, cn2);
                uint32_t goA = pack_h2(0.5f * go1, 0.5f * go0);
                uint32_t goB = pack_h2(0.5f * go3, 0.5f * go2);
                uint32_t tcA = h2tanh(cnA), tcB = h2tanh(cnB);
                uint32_t tgA = h2tanh(goA), tgB = h2tanh(goB);
                uint32_t soA = h2fma(tgA, H2_HALF, H2_HALF);
                uint32_t soB = h2fma(tgB, H2_HALF, H2_HALF);
                uint32_t hnA = h2mul(soA, tcA);
                uint32_t hnB = h2mul(soB, tcB);

                if (u0) {
                    c0[m] = cn0;
                    *(uint16_t*)(smraw + OFF_A + g0 * 144 + cell * 2) =
                        (uint16_t)(hnA & 0xFFFFu);
                }
                if (u1) {
                    c1[m] = cn1;
                    *(uint16_t*)(smraw + OFF_A + g1 * 144 + cell * 2) =
                        (uint16_t)(hnA >> 16);
                }
                if (u2) {
                    c2[m] = cn2;
                    *(uint16_t*)(smraw + OFF_A + g2 * 144 + cell * 2) =
                        (uint16_t)(hnB & 0xFFFFu);
                }
                if (u3) {
                    c3[m] = cn3;
                    *(uint16_t*)(smraw + OFF_A + g3 * 144 + cell * 2) =
                        (uint16_t)(hnB >> 16);
                }
            }
        }
        // no barrier: A rows warp-private, B/xw read-only
    }

    __syncthreads();   // all warps done before cross-warp A reads

    // output: h fp16 from A -> fp32 out[perm[w]][dir*50+cell]
    for (int i = tid; i < NWB * HH; i += NTH) {
        int w = i / HH, cell = i - w * HH;
        int p = sPerm[w];
        if (p >= 0) {
            float hv = __half2float(*(const __half*)(smraw + OFF_A + w * 144 + cell * 2));
            out[(size_t)p * (2 * HH) + dir * HH + cell] = hv;
        }
    }
}

// ---------- launcher ----------
extern "C" void kernel_launch(void* const* d_in, const int* in_sizes, int n_in,
                              void* d_out, int out_size) {
    const int*   chars = (const int*)d_in[0];
    const int*   lens  = (const int*)d_in[1];
    const float* emb   = (const float*)d_in[2];
    const float* Wih_f = (const float*)d_in[3];
    const float* Whh_f = (const float*)d_in[4];
    const float* bih_f = (const float*)d_in[5];
    const float* bhh_f = (const float*)d_in[6];
    const float* Wih_b = (const float*)d_in[7];
    const float* Whh_b = (const float*)d_in[8];
    const float* bih_b = (const float*)d_in[9];
    const float* bhh_b = (const float*)d_in[10];
    float* out = (float*)d_out;

    const int N = in_sizes[1];

    {
        int telems = 2 * VV * HH + 2 * NB * KP;       // 20000 + 26624
        int tblocks = (telems + AUXTH - 1) / AUXTH;   // 92
        aux_all<<<1 + tblocks, AUXTH>>>(lens, N, emb, Wih_f, bih_f, bhh_f,
                                        Wih_b, bih_b, bhh_b, Whh_f, Whh_b);
    }

    cudaFuncSetAttribute(lstm_mma_kernel,
                         cudaFuncAttributeMaxDynamicSharedMemorySize, SMEM_BYTES);
    dim3 grid((N + NWB - 1) / NWB, 2);
    lstm_mma_kernel<<<grid, NTH, SMEM_BYTES>>>(chars, lens, out, N);
}

// round 15
// speedup vs baseline: 1.4734x; 1.4734x over previous
#include <cuda_runtime.h>
#include <cuda_fp16.h>
#include <cstdint>

// CharBiLSTMEmbedder: N=32768, T=20, E=H=50, V=200, out [N,2H] fp32.
//
// Round-15 = Round-13 (best config: 512 thr / 16 warps / 16 rows per warp) +
// intra-warp latency fixes:
//  - manual B-fragment double buffer: LDSM for m+1 issues before MMA/epilogue
//    of m (all ldsm volatile -> source order preserved -> deterministic)
//  - mma_f16 non-volatile (pure reg function) -> ptxas may interleave with
//    epilogue math
// Numerics bit-identical to R13 (rel_err must remain 6.8159e-4).

#define TT 20
#define HH 50
#define EE 50
#define VV 200
#define G4 200
#define NB 208           // padded B rows (26 tiles x 8)
#define KP 64            // padded K
#define NWB 256          // words per CTA
#define NTH 512
#define NMAX 65536
#define AUXTH 512

// smem offsets (A/B rows padded to 144B)
#define OFF_A    0        // 256*144 = 36864
#define OFF_B    36864    // 208*144 = 29952 -> 66816
#define OFF_XW   66816    // 200*200*2 = 80000 -> 146816
#define OFF_CH   146816   // 20*256 = 5120 -> 151936
#define OFF_LEN  151936   // 1024
#define OFF_PERM 152960   // 1024
#define SMEM_BYTES 153984

#define H2_HALF 0x38003800u   // (0.5, 0.5) fp16x2

__device__ __half g_xwh[2 * VV * G4];       // [dir][v][cell*4+gate]
__device__ __half g_wf[2 * NB * KP];        // [dir][n(gate-pair layout)][k]
__device__ int g_perm[NMAX];

// ---------- helpers ----------
__device__ __forceinline__ uint32_t s2u(const void* p) {
    uint32_t a;
    asm("{ .reg .u64 t; cvta.to.shared.u64 t, %1; cvt.u32.u64 %0, t; }"
        : "=r"(a) : "l"(p));
    return a;
}
__device__ __forceinline__ float tanha(float x) {
    float y; asm("tanh.approx.f32 %0, %1;" : "=f"(y) : "f"(x)); return y;
}
__device__ __forceinline__ float sigt(float x) {
    return fmaf(tanha(0.5f * x), 0.5f, 0.5f);
}
__device__ __forceinline__ uint32_t pack_h2(float hi, float lo) {
    uint32_t d;
    asm("cvt.rn.f16x2.f32 %0, %1, %2;" : "=r"(d) : "f"(hi), "f"(lo));
    return d;
}
__device__ __forceinline__ uint32_t h2tanh(uint32_t x) {
    uint32_t y; asm("tanh.approx.f16x2 %0, %1;" : "=r"(y) : "r"(x)); return y;
}
__device__ __forceinline__ uint32_t h2fma(uint32_t a, uint32_t b, uint32_t c) {
    uint32_t d;
    asm("fma.rn.f16x2 %0, %1, %2, %3;" : "=r"(d) : "r"(a), "r"(b), "r"(c));
    return d;
}
__device__ __forceinline__ uint32_t h2mul(uint32_t a, uint32_t b) {
    uint32_t d;
    asm("mul.rn.f16x2 %0, %1, %2;" : "=r"(d) : "r"(a), "r"(b));
    return d;
}
__device__ __forceinline__ void ldsm4(uint32_t& r0, uint32_t& r1, uint32_t& r2,
                                      uint32_t& r3, uint32_t addr) {
    asm volatile("ldmatrix.sync.aligned.m8n8.x4.shared.b16 {%0,%1,%2,%3}, [%4];"
                 : "=r"(r0), "=r"(r1), "=r"(r2), "=r"(r3) : "r"(addr));
}
// NON-volatile: pure register function -> scheduler freedom
__device__ __forceinline__ void mma_f16(float& d0, float& d1, float& d2, float& d3,
                                        uint32_t a0, uint32_t a1, uint32_t a2, uint32_t a3,
                                        uint32_t b0, uint32_t b1) {
    asm("mma.sync.aligned.m16n8k16.row.col.f32.f16.f16.f32 "
        "{%0,%1,%2,%3}, {%4,%5,%6,%7}, {%8,%9}, {%0,%1,%2,%3};"
        : "+f"(d0), "+f"(d1), "+f"(d2), "+f"(d3)
        : "r"(a0), "r"(a1), "r"(a2), "r"(a3), "r"(b0), "r"(b1));
}
// B fragments of gate-pair tile m: IF (k0-31, k32-63), GO (k0-31, k32-63)
__device__ __forceinline__ void load_b(uint32_t* b, uint32_t bAddr, int m) {
    const uint32_t bIF = bAddr + (uint32_t)(m * 8) * 144;
    const uint32_t bGO = bIF + 104u * 144u;
    ldsm4(b[0], b[1], b[2], b[3], bIF);
    ldsm4(b[4], b[5], b[6], b[7], bIF + 64);
    ldsm4(b[8], b[9], b[10], b[11], bGO);
    ldsm4(b[12], b[13], b[14], b[15], bGO + 64);
}

// ---------- fused aux: block 0 = counting sort; blocks 1.. = tables ----------
__global__ void __launch_bounds__(AUXTH)
aux_all(const int* __restrict__ lens, int N,
        const float* __restrict__ emb,
        const float* __restrict__ Wih_f, const float* __restrict__ bih_f,
        const float* __restrict__ bhh_f,
        const float* __restrict__ Wih_b, const float* __restrict__ bih_b,
        const float* __restrict__ bhh_b,
        const float* __restrict__ Whh_f, const float* __restrict__ Whh_b) {
    const int tid = threadIdx.x;
    if (blockIdx.x == 0) {
        __shared__ int hist[TT + 1];
        __shared__ int base[TT + 1];
        if (tid <= TT) hist[tid] = 0;
        __syncthreads();
        for (int i = tid; i < N; i += AUXTH) {
            int L = lens[i]; if (L < 0) L = 0; if (L > TT) L = TT;
            atomicAdd(&hist[L], 1);
        }
        __syncthreads();
        if (tid == 0) {
            int off = 0;
            for (int q = TT; q >= 0; --q) { base[q] = off; off += hist[q]; }
        }
        __syncthreads();
        for (int i = tid; i < N; i += AUXTH) {
            int L = lens[i]; if (L < 0) L = 0; if (L > TT) L = TT;
            int p = atomicAdd(&base[L], 1);
            g_perm[p] = i;        // bin order = atomic order; outputs perm-invariant
        }
        return;
    }

    int idx = (blockIdx.x - 1) * AUXTH + tid;
    if (idx < 2 * VV * HH) {              // xw: all 4 gates of (dir, v, j)
        int dir = idx / (VV * HH);
        int r   = idx % (VV * HH);
        int v   = r / HH, j = r % HH;
        const float* Wih = dir ? Wih_b : Wih_f;
        const float* bih = dir ? bih_b : bih_f;
        const float* bhh = dir ? bhh_b : bhh_f;
        float a0 = 0.f, a1 = 0.f, a2 = 0.f, a3 = 0.f;
        if (v != 0) {                     // padding_idx 0 -> zero embedding row
            const float2* er = (const float2*)(emb + v * EE);
            const float2* w0 = (const float2*)(Wih + (0 * HH + j) * EE);
            const float2* w1 = (const float2*)(Wih + (1 * HH + j) * EE);
            const float2* w2 = (const float2*)(Wih + (2 * HH + j) * EE);
            const float2* w3 = (const float2*)(Wih + (3 * HH + j) * EE);
#pragma unroll
            for (int e = 0; e < EE / 2; ++e) {
                float2 ev = er[e];
                float2 x0 = w0[e], x1 = w1[e], x2 = w2[e], x3 = w3[e];
                a0 += ev.x * x0.x + ev.y * x0.y;
                a1 += ev.x * x1.x + ev.y * x1.y;
                a2 += ev.x * x2.x + ev.y * x2.y;
                a3 += ev.x * x3.x + ev.y * x3.y;
            }
        }
        __half* dst = g_xwh + (size_t)dir * VV * G4 + v * G4 + j * 4;
        dst[0] = __float2half(a0 + bih[0 * HH + j] + bhh[0 * HH + j]);
        dst[1] = __float2half(a1 + bih[1 * HH + j] + bhh[1 * HH + j]);
        dst[2] = __float2half(a2 + bih[2 * HH + j] + bhh[2 * HH + j]);
        dst[3] = __float2half(a3 + bih[3 * HH + j] + bhh[3 * HH + j]);
        return;
    }
    int i2 = idx - 2 * VV * HH;
    if (i2 >= 2 * NB * KP) return;        // W fp16: gate-pair layout
    int dir = i2 / (NB * KP);
    int r   = i2 % (NB * KP);
    int n   = r / KP;
    int k   = r % KP;
    int gate, cell;
    if (n < 104) {                        // (i,f) tiles
        int m = n >> 3, j = n & 7;
        gate = (j & 1) ? 1 : 0;
        cell = 4 * m + (j >> 1);
    } else {                              // (g,o) tiles
        int n2 = n - 104;
        int m = n2 >> 3, j = n2 & 7;
        gate = (j & 1) ? 3 : 2;
        cell = 4 * m + (j >> 1);
    }
    const float* Whh = dir ? Whh_b : Whh_f;
    float w = (cell < HH && k < HH) ? Whh[(gate * HH + cell) * HH + k] : 0.0f;
    g_wf[i2] = __float2half(w);
}

// ---------- main kernel ----------
__global__ void __launch_bounds__(NTH, 1)
lstm_mma_kernel(const int* __restrict__ chars, const int* __restrict__ lens,
                float* __restrict__ out, int N) {
    extern __shared__ __align__(16) unsigned char smraw[];
    const uint32_t su = s2u(smraw);
    __half* sXWH = (__half*)(smraw + OFF_XW);
    unsigned char* sCh = smraw + OFF_CH;
    int* sLen  = (int*)(smraw + OFF_LEN);
    int* sPerm = (int*)(smraw + OFF_PERM);

    const int tid   = threadIdx.x;
    const int dir   = blockIdx.y;
    const int wbase = blockIdx.x * NWB;

    if (tid < NWB) {
        int gi = wbase + tid;
        int p = (gi < N) ? g_perm[gi] : -1;
        sPerm[tid] = p;
        int L = (p >= 0) ? lens[p] : 0;
        if (L < 0) L = 0; if (L > TT) L = TT;
        sLen[tid] = L;
    }
    // zero A (h starts 0; k-pad stays 0)
    {
        uint4* a4 = (uint4*)(smraw + OFF_A);
        uint4 z = make_uint4(0, 0, 0, 0);
        for (int i = tid; i < (NWB * 144) / 16; i += NTH) a4[i] = z;
    }
    // stage B (rows of 64 fp16 = 8 uint4, stride 144B)
    {
        const uint4* src = (const uint4*)(g_wf + (size_t)dir * NB * KP);
        for (int i = tid; i < NB * 8; i += NTH) {
            int n = i >> 3, j = i & 7;
            *(uint4*)(smraw + OFF_B + n * 144 + j * 16) = src[i];
        }
    }
    // stage xw fp16 (5000 uint4)
    {
        const uint4* src = (const uint4*)(g_xwh + (size_t)dir * VV * G4);
        uint4* dst = (uint4*)sXWH;
        for (int i = tid; i < (VV * G4 * 2) / 16; i += NTH) dst[i] = src[i];
    }
    __syncthreads();
    for (int i = tid; i < NWB * TT; i += NTH) {
        int w = i / TT, t = i % TT;
        int p = sPerm[w];
        sCh[t * NWB + w] = (unsigned char)((p >= 0) ? chars[p * TT + t] : 0);
    }
    __syncthreads();

    const int warp = tid >> 5, lane = tid & 31;
    const int R0 = warp * 16;
    const int tig = lane & 3;
    const int g0 = R0 + (lane >> 2);            // word row A
    const int g1 = g0 + 8;                      // word row B
    const int len0 = sLen[g0], len1 = sLen[g1];
    const int warpmax = sLen[R0];               // sorted desc

    const uint32_t aBase = su + OFF_A + (uint32_t)(R0 + (lane & 15)) * 144
                         + (uint32_t)((lane >> 4) & 1) * 16;
    const uint32_t bAddr = su + OFF_B + (uint32_t)(lane & 7) * 144
                         + (uint32_t)(lane >> 3) * 16;

    float creg0[13], creg1[13];
#pragma unroll
    for (int i = 0; i < 13; ++i) { creg0[i] = 0.f; creg1[i] = 0.f; }

    for (int s = 0; s < warpmax; ++s) {
        // B prefetch for m=0, then A fragments
        uint32_t bcur[16], bnxt[16];
        load_b(bcur, bAddr, 0);

        uint32_t a[4][4];
#pragma unroll
        for (int kk = 0; kk < 4; ++kk)
            ldsm4(a[kk][0], a[kk][1], a[kk][2], a[kk][3], aBase + kk * 32);

        int t0 = dir ? (len0 - 1 - s) : s; if (t0 < 0) t0 = 0;
        int t1 = dir ? (len1 - 1 - s) : s; if (t1 < 0) t1 = 0;
        const int ch0 = sCh[t0 * NWB + g0];
        const int ch1 = sCh[t1 * NWB + g1];
        const bool u0 = (s < len0), u1 = (s < len1);
        const __half* xr0 = sXWH + ch0 * G4;
        const __half* xr1 = sXWH + ch1 * G4;

#pragma unroll
        for (int m = 0; m < 13; ++m) {
            // prefetch next tile's B before using this tile's (hide LDSM latency)
            if (m < 12) load_b(bnxt, bAddr, m + 1);

            const int cell = 4 * m + tig;
            float dif0 = 0.f, dif1 = 0.f, dif2 = 0.f, dif3 = 0.f;
            float dgo0 = 0.f, dgo1 = 0.f, dgo2 = 0.f, dgo3 = 0.f;
            mma_f16(dif0, dif1, dif2, dif3, a[0][0], a[0][1], a[0][2], a[0][3],
                    bcur[0], bcur[1]);
            mma_f16(dgo0, dgo1, dgo2, dgo3, a[0][0], a[0][1], a[0][2], a[0][3],
                    bcur[8], bcur[9]);
            mma_f16(dif0, dif1, dif2, dif3, a[1][0], a[1][1], a[1][2], a[1][3],
                    bcur[2], bcur[3]);
            mma_f16(dgo0, dgo1, dgo2, dgo3, a[1][0], a[1][1], a[1][2], a[1][3],
                    bcur[10], bcur[11]);
            mma_f16(dif0, dif1, dif2, dif3, a[2][0], a[2][1], a[2][2], a[2][3],
                    bcur[4], bcur[5]);
            mma_f16(dgo0, dgo1, dgo2, dgo3, a[2][0], a[2][1], a[2][2], a[2][3],
                    bcur[12], bcur[13]);
            mma_f16(dif0, dif1, dif2, dif3, a[3][0], a[3][1], a[3][2], a[3][3],
                    bcur[6], bcur[7]);
            mma_f16(dgo0, dgo1, dgo2, dgo3, a[3][0], a[3][1], a[3][2], a[3][3],
                    bcur[14], bcur[15]);

            if (m < 12 || tig < 2) {             // cell < 50
                uint2 xq0 = *(const uint2*)(xr0 + cell * 4);
                uint2 xq1 = *(const uint2*)(xr1 + cell * 4);
                float2 xif0 = __half22float2(*(__half2*)&xq0.x);
                float2 xgo0 = __half22float2(*(__half2*)&xq0.y);
                float2 xif1 = __half22float2(*(__half2*)&xq1.x);
                float2 xgo1 = __half22float2(*(__half2*)&xq1.y);
                // c-channel fp32 (recurrence-critical path)
                float gi0 = dif0 + xif0.x, gf0 = dif1 + xif0.y;
                float gg0 = dgo0 + xgo0.x, go0 = dgo1 + xgo0.y;
                float gi1 = dif2 + xif1.x, gf1 = dif3 + xif1.y;
                float gg1 = dgo2 + xgo1.x, go1 = dgo3 + xgo1.y;
                float cn0 = sigt(gf0) * creg0[m] + sigt(gi0) * tanha(gg0);
                float cn1 = sigt(gf1) * creg1[m] + sigt(gi1) * tanha(gg1);
                // h-channel packed f16x2: h = sigma(o) * tanh(c)
                uint32_t cn2 = pack_h2(cn1, cn0);
                uint32_t go2 = pack_h2(0.5f * go1, 0.5f * go0);
                uint32_t tcn = h2tanh(cn2);
                uint32_t tgo = h2tanh(go2);
                uint32_t so2 = h2fma(tgo, H2_HALF, H2_HALF);
                uint32_t hn2 = h2mul(so2, tcn);
                if (u0) {
                    creg0[m] = cn0;
                    *(uint16_t*)(smraw + OFF_A + g0 * 144 + cell * 2) =
                        (uint16_t)(hn2 & 0xFFFFu);
                }
                if (u1) {
                    creg1[m] = cn1;
                    *(uint16_t*)(smraw + OFF_A + g1 * 144 + cell * 2) =
                        (uint16_t)(hn2 >> 16);
                }
            }

            // rotate buffers (renamed away by ptxas after full unroll)
#pragma unroll
            for (int i = 0; i < 16; ++i) bcur[i] = bnxt[i];
        }
        // no barrier: A rows warp-private, B/xw read-only
    }

    __syncthreads();   // all warps done before cross-warp A reads

    // output: h fp16 from A -> fp32 out[perm[w]][dir*50+cell]
    for (int i = tid; i < NWB * HH; i += NTH) {
        int w = i / HH, cell = i - w * HH;
        int p = sPerm[w];
        if (p >= 0) {
            float hv = __half2float(*(const __half*)(smraw + OFF_A + w * 144 + cell * 2));
            out[(size_t)p * (2 * HH) + dir * HH + cell] = hv;
        }
    }
}

// ---------- launcher ----------
extern "C" void kernel_launch(void* const* d_in, const int* in_sizes, int n_in,
                              void* d_out, int out_size) {
    const int*   chars = (const int*)d_in[0];
    const int*   lens  = (const int*)d_in[1];
    const float* emb   = (const float*)d_in[2];
    const float* Wih_f = (const float*)d_in[3];
    const float* Whh_f = (const float*)d_in[4];
    const float* bih_f = (const float*)d_in[5];
    const float* bhh_f = (const float*)d_in[6];
    const float* Wih_b = (const float*)d_in[7];
    const float* Whh_b = (const float*)d_in[8];
    const float* bih_b = (const float*)d_in[9];
    const float* bhh_b = (const float*)d_in[10];
    float* out = (float*)d_out;

    const int N = in_sizes[1];

    {
        int telems = 2 * VV * HH + 2 * NB * KP;       // 20000 + 26624
        int tblocks = (telems + AUXTH - 1) / AUXTH;   // 92
        aux_all<<<1 + tblocks, AUXTH>>>(lens, N, emb, Wih_f, bih_f, bhh_f,
                                        Wih_b, bih_b, bhh_b, Whh_f, Whh_b);
    }

    cudaFuncSetAttribute(lstm_mma_kernel,
                         cudaFuncAttributeMaxDynamicSharedMemorySize, SMEM_BYTES);
    dim3 grid((N + NWB - 1) / NWB, 2);
    lstm_mma_kernel<<<grid, NTH, SMEM_BYTES>>>(chars, lens, out, N);
}

// round 16
// speedup vs baseline: 1.4770x; 1.0025x over previous
#include <cuda_runtime.h>
#include <cuda_fp16.h>
#include <cstdint>

// CharBiLSTMEmbedder: N=32768, T=20, E=H=50, V=200, out [N,2H] fp32.
//
// Round-16 = R13 config (512 thr / 16 warps / 16 rows per warp, no B prefetch)
// + xw folded into the MMA accumulator init (deletes 104 FADD/warp-step and
// one FADD from the epilogue chain) + non-volatile mma (R15).

#define TT 20
#define HH 50
#define EE 50
#define VV 200
#define G4 200
#define NB 208
#define KP 64
#define NWB 256
#define NTH 512
#define NMAX 65536
#define AUXTH 512

#define OFF_A    0
#define OFF_B    36864
#define OFF_XW   66816
#define OFF_CH   146816
#define OFF_LEN  151936
#define OFF_PERM 152960
#define SMEM_BYTES 153984

#define H2_HALF 0x38003800u

__device__ __half g_xwh[2 * VV * G4];
__device__ __half g_wf[2 * NB * KP];
__device__ int g_perm[NMAX];

__device__ __forceinline__ uint32_t s2u(const void* p) {
    uint32_t a;
    asm("{ .reg .u64 t; cvta.to.shared.u64 t, %1; cvt.u32.u64 %0, t; }"
        : "=r"(a) : "l"(p));
    return a;
}
__device__ __forceinline__ float tanha(float x) {
    float y; asm("tanh.approx.f32 %0, %1;" : "=f"(y) : "f"(x)); return y;
}
__device__ __forceinline__ float sigt(float x) {
    return fmaf(tanha(0.5f * x), 0.5f, 0.5f);
}
__device__ __forceinline__ uint32_t pack_h2(float hi, float lo) {
    uint32_t d;
    asm("cvt.rn.f16x2.f32 %0, %1, %2;" : "=r"(d) : "f"(hi), "f"(lo));
    return d;
}
__device__ __forceinline__ uint32_t h2tanh(uint32_t x) {
    uint32_t y; asm("tanh.approx.f16x2 %0, %1;" : "=r"(y) : "r"(x)); return y;
}
__device__ __forceinline__ uint32_t h2fma(uint32_t a, uint32_t b, uint32_t c) {
    uint32_t d;
    asm("fma.rn.f16x2 %0, %1, %2, %3;" : "=r"(d) : "r"(a), "r"(b), "r"(c));
    return d;
}
__device__ __forceinline__ uint32_t h2mul(uint32_t a, uint32_t b) {
    uint32_t d;
    asm("mul.rn.f16x2 %0, %1, %2;" : "=r"(d) : "r"(a), "r"(b));
    return d;
}
__device__ __forceinline__ void ldsm4(uint32_t& r0, uint32_t& r1, uint32_t& r2,
                                      uint32_t& r3, uint32_t addr) {
    asm volatile("ldmatrix.sync.aligned.m8n8.x4.shared.b16 {%0,%1,%2,%3}, [%4];"
                 : "=r"(r0), "=r"(r1), "=r"(r2), "=r"(r3) : "r"(addr));
}
__device__ __forceinline__ void mma_f16(float& d0, float& d1, float& d2, float& d3,
                                        uint32_t a0, uint32_t a1, uint32_t a2, uint32_t a3,
                                        uint32_t b0, uint32_t b1) {
    asm("mma.sync.aligned.m16n8k16.row.col.f32.f16.f16.f32 "
        "{%0,%1,%2,%3}, {%4,%5,%6,%7}, {%8,%9}, {%0,%1,%2,%3};"
        : "+f"(d0), "+f"(d1), "+f"(d2), "+f"(d3)
        : "r"(a0), "r"(a1), "r"(a2), "r"(a3), "r"(b0), "r"(b1));
}

__global__ void __launch_bounds__(AUXTH)
aux_all(const int* __restrict__ lens, int N,
        const float* __restrict__ emb,
        const float* __restrict__ Wih_f, const float* __restrict__ bih_f,
        const float* __restrict__ bhh_f,
        const float* __restrict__ Wih_b, const float* __restrict__ bih_b,
        const float* __restrict__ bhh_b,
        const float* __restrict__ Whh_f, const float* __restrict__ Whh_b) {
    const int tid = threadIdx.x;
    if (blockIdx.x == 0) {
        __shared__ int hist[TT + 1];
        __shared__ int base[TT + 1];
        if (tid <= TT) hist[tid] = 0;
        __syncthreads();
        for (int i = tid; i < N; i += AUXTH) {
            int L = lens[i]; if (L < 0) L = 0; if (L > TT) L = TT;
            atomicAdd(&hist[L], 1);
        }
        __syncthreads();
        if (tid == 0) {
            int off = 0;
            for (int q = TT; q >= 0; --q) { base[q] = off; off += hist[q]; }
        }
        __syncthreads();
        for (int i = tid; i < N; i += AUXTH) {
            int L = lens[i]; if (L < 0) L = 0; if (L > TT) L = TT;
            int p = atomicAdd(&base[L], 1);
            g_perm[p] = i;
        }
        return;
    }

    int idx = (blockIdx.x - 1) * AUXTH + tid;
    if (idx < 2 * VV * HH) {
        int dir = idx / (VV * HH);
        int r   = idx % (VV * HH);
        int v   = r / HH, j = r % HH;
        const float* Wih = dir ? Wih_b : Wih_f;
        const float* bih = dir ? bih_b : bih_f;
        const float* bhh = dir ? bhh_b : bhh_f;
        float a0 = 0.f, a1 = 0.f, a2 = 0.f, a3 = 0.f;
        if (v != 0) {
            const float2* er = (const float2*)(emb + v * EE);
            const float2* w0 = (const float2*)(Wih + (0 * HH + j) * EE);
            const float2* w1 = (const float2*)(Wih + (1 * HH + j) * EE);
            const float2* w2 = (const float2*)(Wih + (2 * HH + j) * EE);
            const float2* w3 = (const float2*)(Wih + (3 * HH + j) * EE);
#pragma unroll
            for (int e = 0; e < EE / 2; ++e) {
                float2 ev = er[e];
                float2 x0 = w0[e], x1 = w1[e], x2 = w2[e], x3 = w3[e];
                a0 += ev.x * x0.x + ev.y * x0.y;
                a1 += ev.x * x1.x + ev.y * x1.y;
                a2 += ev.x * x2.x + ev.y * x2.y;
                a3 += ev.x * x3.x + ev.y * x3.y;
            }
        }
        __half* dst = g_xwh + (size_t)dir * VV * G4 + v * G4 + j * 4;
        dst[0] = __float2half(a0 + bih[0 * HH + j] + bhh[0 * HH + j]);
        dst[1] = __float2half(a1 + bih[1 * HH + j] + bhh[1 * HH + j]);
        dst[2] = __float2half(a2 + bih[2 * HH + j] + bhh[2 * HH + j]);
        dst[3] = __float2half(a3 + bih[3 * HH + j] + bhh[3 * HH + j]);
        return;
    }
    int i2 = idx - 2 * VV * HH;
    if (i2 >= 2 * NB * KP) return;
    int dir = i2 / (NB * KP);
    int r   = i2 % (NB * KP);
    int n   = r / KP;
    int k   = r % KP;
    int gate, cell;
    if (n < 104) {
        int m = n >> 3, j = n & 7;
        gate = (j & 1) ? 1 : 0;
        cell = 4 * m + (j >> 1);
    } else {
        int n2 = n - 104;
        int m = n2 >> 3, j = n2 & 7;
        gate = (j & 1) ? 3 : 2;
        cell = 4 * m + (j >> 1);
    }
    const float* Whh = dir ? Whh_b : Whh_f;
    float w = (cell < HH && k < HH) ? Whh[(gate * HH + cell) * HH + k] : 0.0f;
    g_wf[i2] = __float2half(w);
}

__global__ void __launch_bounds__(NTH, 1)
lstm_mma_kernel(const int* __restrict__ chars, const int* __restrict__ lens,
                float* __restrict__ out, int N) {
    extern __shared__ __align__(16) unsigned char smraw[];
    const uint32_t su = s2u(smraw);
    __half* sXWH = (__half*)(smraw + OFF_XW);
    unsigned char* sCh = smraw + OFF_CH;
    int* sLen  = (int*)(smraw + OFF_LEN);
    int* sPerm = (int*)(smraw + OFF_PERM);

    const int tid   = threadIdx.x;
    const int dir   = blockIdx.y;
    const int wbase = blockIdx.x * NWB;

    if (tid < NWB) {
        int gi = wbase + tid;
        int p = (gi < N) ? g_perm[gi] : -1;
        sPerm[tid] = p;
        int L = (p >= 0) ? lens[p] : 0;
        if (L < 0) L = 0; if (L > TT) L = TT;
        sLen[tid] = L;
    }
    {
        uint4* a4 = (uint4*)(smraw + OFF_A);
        uint4 z = make_uint4(0, 0, 0, 0);
        for (int i = tid; i < (NWB * 144) / 16; i += NTH) a4[i] = z;
    }
    {
        const uint4* src = (const uint4*)(g_wf + (size_t)dir * NB * KP);
        for (int i = tid; i < NB * 8; i += NTH) {
            int n = i >> 3, j = i & 7;
            *(uint4*)(smraw + OFF_B + n * 144 + j * 16) = src[i];
        }
    }
    {
        const uint4* src = (const uint4*)(g_xwh + (size_t)dir * VV * G4);
        uint4* dst = (uint4*)sXWH;
        for (int i = tid; i < (VV * G4 * 2) / 16; i += NTH) dst[i] = src[i];
    }
    __syncthreads();
    for (int i = tid; i < NWB * TT; i += NTH) {
        int w = i / TT, t = i % TT;
        int p = sPerm[w];
        sCh[t * NWB + w] = (unsigned char)((p >= 0) ? chars[p * TT + t] : 0);
    }
    __syncthreads();

    const int warp = tid >> 5, lane = tid & 31;
    const int R0 = warp * 16;
    const int tig = lane & 3;
    const int g0 = R0 + (lane >> 2);
    const int g1 = g0 + 8;
    const int len0 = sLen[g0], len1 = sLen[g1];
    const int warpmax = sLen[R0];

    const uint32_t aBase = su + OFF_A + (uint32_t)(R0 + (lane & 15)) * 144
                         + (uint32_t)((lane >> 4) & 1) * 16;
    const uint32_t bAddr = su + OFF_B + (uint32_t)(lane & 7) * 144
                         + (uint32_t)(lane >> 3) * 16;

    float creg0[13], creg1[13];
#pragma unroll
    for (int i = 0; i < 13; ++i) { creg0[i] = 0.f; creg1[i] = 0.f; }

    for (int s = 0; s < warpmax; ++s) {
        uint32_t a[4][4];
#pragma unroll
        for (int kk = 0; kk < 4; ++kk)
            ldsm4(a[kk][0], a[kk][1], a[kk][2], a[kk][3], aBase + kk * 32);

        int t0 = dir ? (len0 - 1 - s) : s; if (t0 < 0) t0 = 0;
        int t1 = dir ? (len1 - 1 - s) : s; if (t1 < 0) t1 = 0;
        const int ch0 = sCh[t0 * NWB + g0];
        const int ch1 = sCh[t1 * NWB + g1];
        const bool u0 = (s < len0), u1 = (s < len1);
        const __half* xr0 = sXWH + ch0 * G4;
        const __half* xr1 = sXWH + ch1 * G4;

#pragma unroll
        for (int m = 0; m < 13; ++m) {
            const int cell = 4 * m + tig;
            const int cellc = (cell < HH) ? cell : 0;   // pad lanes: safe index
            uint2 xq0 = *(const uint2*)(xr0 + cellc * 4);
            uint2 xq1 = *(const uint2*)(xr1 + cellc * 4);
            float2 xif0 = __half22float2(*(__half2*)&xq0.x);
            float2 xgo0 = __half22float2(*(__half2*)&xq0.y);
            float2 xif1 = __half22float2(*(__half2*)&xq1.x);
            float2 xgo1 = __half22float2(*(__half2*)&xq1.y);

            const uint32_t bIF = bAddr + (uint32_t)(m * 8) * 144;
            const uint32_t bGO = bIF + (uint32_t)(104) * 144;
            uint32_t p0, p1, p2, p3, q0, q1, q2, q3;
            uint32_t r0, r1, r2, r3, w0, w1, w2, w3;
            ldsm4(p0, p1, p2, p3, bIF);
            ldsm4(q0, q1, q2, q3, bIF + 64);
            ldsm4(r0, r1, r2, r3, bGO);
            ldsm4(w0, w1, w2, w3, bGO + 64);

            // accumulators start at xw: d = xw + h@W
            float dif0 = xif0.x, dif1 = xif0.y, dif2 = xif1.x, dif3 = xif1.y;
            float dgo0 = xgo0.x, dgo1 = xgo0.y, dgo2 = xgo1.x, dgo3 = xgo1.y;
            mma_f16(dif0, dif1, dif2, dif3, a[0][0], a[0][1], a[0][2], a[0][3], p0, p1);
            mma_f16(dgo0, dgo1, dgo2, dgo3, a[0][0], a[0][1], a[0][2], a[0][3], r0, r1);
            mma_f16(dif0, dif1, dif2, dif3, a[1][0], a[1][1], a[1][2], a[1][3], p2, p3);
            mma_f16(dgo0, dgo1, dgo2, dgo3, a[1][0], a[1][1], a[1][2], a[1][3], r2, r3);
            mma_f16(dif0, dif1, dif2, dif3, a[2][0], a[2][1], a[2][2], a[2][3], q0, q1);
            mma_f16(dgo0, dgo1, dgo2, dgo3, a[2][0], a[2][1], a[2][2], a[2][3], w0, w1);
            mma_f16(dif0, dif1, dif2, dif3, a[3][0], a[3][1], a[3][2], a[3][3], q2, q3);
            mma_f16(dgo0, dgo1, dgo2, dgo3, a[3][0], a[3][1], a[3][2], a[3][3], w2, w3);

            if (m < 12 || tig < 2) {             // cell < 50
                // gates ARE the accumulators (xw already folded in)
                float cn0 = sigt(dif1) * creg0[m] + sigt(dif0) * tanha(dgo0);
                float cn1 = sigt(dif3) * creg1[m] + sigt(dif2) * tanha(dgo2);
                uint32_t cn2 = pack_h2(cn1, cn0);
                uint32_t go2 = pack_h2(0.5f * dgo3, 0.5f * dgo1);
                uint32_t tcn = h2tanh(cn2);
                uint32_t tgo = h2tanh(go2);
                uint32_t so2 = h2fma(tgo, H2_HALF, H2_HALF);
                uint32_t hn2 = h2mul(so2, tcn);
                if (u0) {
                    creg0[m] = cn0;
                    *(uint16_t*)(smraw + OFF_A + g0 * 144 + cell * 2) =
                        (uint16_t)(hn2 & 0xFFFFu);
                }
                if (u1) {
                    creg1[m] = cn1;
                    *(uint16_t*)(smraw + OFF_A + g1 * 144 + cell * 2) =
                        (uint16_t)(hn2 >> 16);
                }
            }
        }
    }

    __syncthreads();

    for (int i = tid; i < NWB * HH; i += NTH) {
        int w = i / HH, cell = i - w * HH;
        int p = sPerm[w];
        if (p >= 0) {
            float hv = __half2float(*(const __half*)(smraw + OFF_A + w * 144 + cell * 2));
            out[(size_t)p * (2 * HH) + dir * HH + cell] = hv;
        }
    }
}

extern "C" void kernel_launch(void* const* d_in, const int* in_sizes, int n_in,
                              void* d_out, int out_size) {
    const int*   chars = (const int*)d_in[0];
    const int*   lens  = (const int*)d_in[1];
    const float* emb   = (const float*)d_in[2];
    const float* Wih_f = (const float*)d_in[3];
    const float* Whh_f = (const float*)d_in[4];
    const float* bih_f = (const float*)d_in[5];
    const float* bhh_f = (const float*)d_in[6];
    const float* Wih_b = (const float*)d_in[7];
    const float* Whh_b = (const float*)d_in[8];
    const float* bih_b = (const float*)d_in[9];
    const float* bhh_b = (const float*)d_in[10];
    float* out = (float*)d_out;

    const int N = in_sizes[1];

    {
        int telems = 2 * VV * HH + 2 * NB * KP;
        int tblocks = (telems + AUXTH - 1) / AUXTH;
        aux_all<<<1 + tblocks, AUXTH>>>(lens, N, emb, Wih_f, bih_f, bhh_f,
                                        Wih_b, bih_b, bhh_b, Whh_f, Whh_b);
    }

    cudaFuncSetAttribute(lstm_mma_kernel,
                         cudaFuncAttributeMaxDynamicSharedMemorySize, SMEM_BYTES);
    dim3 grid((N + NWB - 1) / NWB, 2);
    lstm_mma_kernel<<<grid, NTH, SMEM_BYTES>>>(chars, lens, out, N);
}